// round 14
// baseline (speedup 1.0000x reference)
#include <cuda_runtime.h>
#include <cuda_bf16.h>
#include <cstdint>

#define B_   256
#define T_   10
#define BT_  2560
#define HW_  49
#define VD_  512
#define AD_  128
#define HD_  256

// ---------------------------------------------------------------------------
// Scratch (__device__ globals — allocation-free)
// ---------------------------------------------------------------------------
__device__ float g_aq1[BT_ * VD_];
__device__ float g_aq2[BT_ * HD_];
__device__ float g_m1 [BT_ * VD_];
__device__ float g_scale[BT_ * VD_];

// Pre-split bf16 weight images, K=32 chunks, unpadded 64B rows:
// [n_chunk][k_chunk(16)][128 n-rows][32 k]
__device__ __align__(16) __nv_bfloat16 g_W1h[4 * 16 * 128 * 32];
__device__ __align__(16) __nv_bfloat16 g_W1l[4 * 16 * 128 * 32];
__device__ __align__(16) __nv_bfloat16 g_W2h[2 * 16 * 128 * 32];
__device__ __align__(16) __nv_bfloat16 g_W2l[2 * 16 * 128 * 32];

// Transposed packed fp32 weights for k3
__device__ __align__(16) float4 g_WbT4[128 * 256];
__device__ __align__(16) float4 g_WcT4[64 * 512];

#define CHUNK_ELEMS (128 * 32)           // 4096 bf16 = 8192 B per image chunk
#define ROWB 80                          // smem row stride (32 bf16 + 16B pad)
#define MT_STRIDE (16 * ROWB)            // 1280

// ---------------------------------------------------------------------------
// Helpers (plain sm_103-safe PTX only)
// ---------------------------------------------------------------------------
__device__ __forceinline__ uint32_t smem_u32(const void* p) {
    uint32_t a;
    asm("{ .reg .u64 t; cvta.to.shared.u64 t, %1; cvt.u32.u64 %0, t; }"
        : "=r"(a) : "l"(p));
    return a;
}
__device__ __forceinline__ void ldmx4(uint32_t addr, uint32_t r[4]) {
    asm volatile("ldmatrix.sync.aligned.m8n8.x4.shared.b16 {%0,%1,%2,%3}, [%4];"
                 : "=r"(r[0]), "=r"(r[1]), "=r"(r[2]), "=r"(r[3]) : "r"(addr));
}
__device__ __forceinline__ void mma_bf16(float d[4], const uint32_t a[4],
                                         uint32_t b0, uint32_t b1) {
    asm volatile(
        "mma.sync.aligned.m16n8k16.row.col.f32.bf16.bf16.f32 "
        "{%0,%1,%2,%3},{%4,%5,%6,%7},{%8,%9},{%0,%1,%2,%3};"
        : "+f"(d[0]), "+f"(d[1]), "+f"(d[2]), "+f"(d[3])
        : "r"(a[0]), "r"(a[1]), "r"(a[2]), "r"(a[3]), "r"(b0), "r"(b1));
}
__device__ __forceinline__ void cp16(uint32_t dst, const void* src) {
    asm volatile("cp.async.cg.shared.global [%0], [%1], 16;" :: "r"(dst), "l"(src));
}
#define CP_COMMIT() asm volatile("cp.async.commit_group;" ::: "memory")
#define CP_WAIT0()  asm volatile("cp.async.wait_group 0;" ::: "memory")

__device__ __forceinline__ void split_store(char* Ah, char* Al, int r, int q,
                                            float x0, float x1, float x2, float x3) {
    __nv_bfloat16 h0 = __float2bfloat16(x0), h1 = __float2bfloat16(x1);
    __nv_bfloat16 h2 = __float2bfloat16(x2), h3 = __float2bfloat16(x3);
    __nv_bfloat16 l0 = __float2bfloat16(x0 - __bfloat162float(h0));
    __nv_bfloat16 l1 = __float2bfloat16(x1 - __bfloat162float(h1));
    __nv_bfloat16 l2 = __float2bfloat16(x2 - __bfloat162float(h2));
    __nv_bfloat16 l3 = __float2bfloat16(x3 - __bfloat162float(h3));
    __nv_bfloat162 p;
    char* dh = Ah + r * ROWB + q * 8;
    char* dl = Al + r * ROWB + q * 8;
    p.x = h0; p.y = h1; *(__nv_bfloat162*)dh = p;
    p.x = h2; p.y = h3; *(__nv_bfloat162*)(dh + 4) = p;
    p.x = l0; p.y = l1; *(__nv_bfloat162*)dl = p;
    p.x = l2; p.y = l3; *(__nv_bfloat162*)(dl + 4) = p;
}

// ---------------------------------------------------------------------------
// k0 / kt / k1: unchanged proven pre-pass kernels
// ---------------------------------------------------------------------------
__global__ void __launch_bounds__(256)
k0_wconv(const float* __restrict__ Wv1, const float* __restrict__ Wv2)
{
    int idx = blockIdx.x * 256 + threadIdx.x;
    if (idx < 512 * 512) {
        int c = idx >> 9, k = idx & 511;
        float v = Wv1[idx];
        __nv_bfloat16 h = __float2bfloat16(v);
        __nv_bfloat16 l = __float2bfloat16(v - __bfloat162float(h));
        int nc = c >> 7, nl = c & 127, kc = k >> 5, kk = k & 31;
        size_t d = ((size_t)(nc * 16 + kc) * 128 + nl) * 32 + kk;
        g_W1h[d] = h; g_W1l[d] = l;
    } else if (idx < 512 * 512 + 256 * 512) {
        int e = idx - 512 * 512;
        int j = e >> 9, k = e & 511;
        float v = Wv2[e];
        __nv_bfloat16 h = __float2bfloat16(v);
        __nv_bfloat16 l = __float2bfloat16(v - __bfloat162float(h));
        int nc = j >> 7, nl = j & 127, kc = k >> 5, kk = k & 31;
        size_t d = ((size_t)(nc * 16 + kc) * 128 + nl) * 32 + kk;
        g_W2h[d] = h; g_W2l[d] = l;
    }
}

__global__ void __launch_bounds__(256)
kt_trans(const float* __restrict__ Wb, const float* __restrict__ Wc)
{
    int idx = blockIdx.x * 256 + threadIdx.x;
    if (idx < 128 * 256) {
        int k4 = idx >> 8, j = idx & 255;
        const float* s = Wb + (size_t)j * VD_ + k4 * 4;
        g_WbT4[idx] = make_float4(s[0], s[1], s[2], s[3]);
    } else if (idx < 128 * 256 + 64 * 512) {
        int e = idx - 128 * 256;
        int k4 = e >> 9, c = e & 511;
        const float* s = Wc + (size_t)c * HD_ + k4 * 4;
        g_WcT4[e] = make_float4(s[0], s[1], s[2], s[3]);
    }
}

__global__ void __launch_bounds__(256)
k1_audio(const float* __restrict__ audio,
         const float* __restrict__ Wa1, const float* __restrict__ ba1,
         const float* __restrict__ Wa2, const float* __restrict__ ba2)
{
    __shared__ __align__(16) float af[32][AD_];
    const int tid = threadIdx.x;
    const int bt0 = blockIdx.x * 32;

    for (int idx = tid; idx < 32 * AD_; idx += 256) {
        int i = idx >> 7, k = idx & 127;
        int bt = bt0 + i;
        int b = bt / T_, t = bt - b * T_;
        af[i][k] = audio[((size_t)t * B_ + b) * AD_ + k];
    }
    __syncthreads();

    for (int c = tid; c < VD_; c += 256) {
        const float4* w4 = (const float4*)(Wa1 + (size_t)c * AD_);
        float acc[32];
#pragma unroll
        for (int i = 0; i < 32; ++i) acc[i] = 0.f;
        for (int k4 = 0; k4 < AD_ / 4; ++k4) {
            float4 w = w4[k4];
#pragma unroll
            for (int i = 0; i < 32; ++i) {
                float4 v = *(const float4*)&af[i][k4 * 4];
                acc[i] += v.x * w.x + v.y * w.y + v.z * w.z + v.w * w.w;
            }
        }
        float bias = ba1[c];
#pragma unroll
        for (int i = 0; i < 32; ++i)
            g_aq1[(size_t)(bt0 + i) * VD_ + c] = fmaxf(acc[i] + bias, 0.f);
    }
    {
        int j = tid;
        const float4* w4 = (const float4*)(Wa2 + (size_t)j * AD_);
        float acc[32];
#pragma unroll
        for (int i = 0; i < 32; ++i) acc[i] = 0.f;
        for (int k4 = 0; k4 < AD_ / 4; ++k4) {
            float4 w = w4[k4];
#pragma unroll
            for (int i = 0; i < 32; ++i) {
                float4 v = *(const float4*)&af[i][k4 * 4];
                acc[i] += v.x * w.x + v.y * w.y + v.z * w.z + v.w * w.w;
            }
        }
        float bias = ba2[j];
#pragma unroll
        for (int i = 0; i < 32; ++i)
            g_aq2[(size_t)(bt0 + i) * HD_ + j] = fmaxf(acc[i] + bias, 0.f);
    }
}

// ---------------------------------------------------------------------------
// Templated GEMM mainloop.
//   MT = A row tiles per warp (2 -> M=64 one clip; 4 -> M=128 clip pair,
//        rows 0-48 = clip0, phys rows 64-112 = clip1, pads zeroed)
//   NP = W 64-row halves (2 -> N=128; 4 -> N=256)
// Double-buffered K=32 chunks, one barrier per chunk (R12-proven schedule).
// s_scale only supported for MT=2 (g2).
// ---------------------------------------------------------------------------
template<int NP, int MT>
__device__ __forceinline__ void gemm_mainloop_t(
    float (&acc)[MT][NP * 2][4], char* sm, uint32_t aBase,
    const float* __restrict__ video, const float* s_scale,
    const __nv_bfloat16* wH0, const __nv_bfloat16* wL0,
    const __nv_bfloat16* wH1, const __nv_bfloat16* wL1,
    int bt0, int tid, int lane, int wm, int wn)
{
    constexpr int AROWS  = MT * 32;                 // 64 or 128
    constexpr int OFF_AL_ = AROWS * ROWB;           // 5120 or 10240
    constexpr int OFF_WH_ = 2 * OFF_AL_;
    constexpr int WSZ     = NP * 5120;
    constexpr int OFF_WL_ = OFF_WH_ + WSZ;
    constexpr int BUF_    = OFF_WH_ + 2 * WSZ;
    constexpr int ITEMS   = (MT == 4) ? 784 : 392;  // float4 conv items
    constexpr int NSLOT   = (ITEMS + 255) / 256;
    constexpr int PADW    = (MT == 4) ? 480 : 240;  // pad words (30/15 rows x16)

    // zero pad rows in both buffers, hi+lo
    for (int i = tid; i < PADW; i += 256) {
        int rr = i >> 4, w = (i & 15) * 4;
        int r = (rr < 15) ? (49 + rr) : (113 - 15 + rr);
#pragma unroll
        for (int b = 0; b < 2; ++b) {
            *(uint32_t*)(sm + b * BUF_ + r * ROWB + w) = 0u;
            *(uint32_t*)(sm + b * BUF_ + OFF_AL_ + r * ROWB + w) = 0u;
        }
    }

    // conversion slot state
    int pr_[NSLOT], q_[NSLOT];
    bool ok_[NSLOT];
    const float* vr_[NSLOT];
#pragma unroll
    for (int s = 0; s < NSLOT; ++s) {
        int i = tid + s * 256;
        ok_[s] = (i < ITEMS);
        int ii = ok_[s] ? i : 0;
        int r = ii >> 3, q = ii & 7;
        int clip = (MT == 4 && r >= 49) ? 1 : 0;
        int h = r - clip * 49;
        pr_[s] = r + clip * 15;
        q_[s] = q;
        vr_[s] = video + ((size_t)(bt0 + clip) * HW_ + h) * VD_ + q * 4;
    }

    // per-lane ldmatrix offsets (within a buffer)
    const uint32_t oAh = (uint32_t)((wm * (MT * 16) + (lane & 15)) * ROWB
                        + ((lane >> 4) & 1) * 16);
    const uint32_t oBh = OFF_WH_
                        + (uint32_t)((wn * (NP * 16) + (lane & 7) + ((lane >> 4) & 1) * 8) * ROWB
                        + ((lane >> 3) & 1) * 16);

    auto issue_w = [&](uint32_t dstBase, int kc) {
        const char* sH0 = (const char*)(wH0 + (size_t)kc * CHUNK_ELEMS);
        const char* sL0 = (const char*)(wL0 + (size_t)kc * CHUNK_ELEMS);
        const char* sH1 = (const char*)(wH1 + (size_t)kc * CHUNK_ELEMS);
        const char* sL1 = (const char*)(wL1 + (size_t)kc * CHUNK_ELEMS);
#pragma unroll
        for (int i = tid; i < 512; i += 256) {
            int r = i >> 2, qq = i & 3;
            uint32_t dof = (uint32_t)(r * ROWB + qq * 16);
            int sof = r * 64 + qq * 16;
            cp16(dstBase + OFF_WH_ + dof, sH0 + sof);
            cp16(dstBase + OFF_WL_ + dof, sL0 + sof);
            if (NP == 4) {
                cp16(dstBase + OFF_WH_ + 10240 + dof, sH1 + sof);
                cp16(dstBase + OFF_WL_ + 10240 + dof, sL1 + sof);
            }
        }
    };

    auto convert = [&](char* buf, int kc) {
#pragma unroll
        for (int s = 0; s < NSLOT; ++s) {
            if (!ok_[s]) continue;
            float4 v = *(const float4*)(vr_[s] + kc * 32);
            if (MT == 2 && s_scale) {
                float4 sc = *(const float4*)(s_scale + kc * 32 + q_[s] * 4);
                v.x *= sc.x; v.y *= sc.y; v.z *= sc.z; v.w *= sc.w;
            }
            split_store(buf, buf + OFF_AL_, pr_[s], q_[s], v.x, v.y, v.z, v.w);
        }
    };

    // prologue: chunk 0 into buf0
    convert(sm, 0);
    issue_w(aBase, 0);
    CP_COMMIT();

    for (int kc = 0; kc < 16; ++kc) {
        const int p = kc & 1;
        const uint32_t bp = aBase + p * BUF_;
        char* bq = sm + (p ^ 1) * BUF_;
        CP_WAIT0();
        __syncthreads();

        if (kc < 15) {
            issue_w(aBase + (p ^ 1) * BUF_, kc + 1);
            CP_COMMIT();
        }

        // MMA on chunk kc (buffer p)
#pragma unroll
        for (int ks = 0; ks < 2; ++ks) {
            if (MT == 2) {
                // A-outer (R13-proven ordering for g2)
                uint32_t ah[MT][4], al[MT][4];
#pragma unroll
                for (int mt = 0; mt < MT; ++mt) {
                    ldmx4(bp + oAh + mt * MT_STRIDE + ks * 32, ah[mt]);
                    ldmx4(bp + OFF_AL_ + oAh + mt * MT_STRIDE + ks * 32, al[mt]);
                }
#pragma unroll
                for (int np = 0; np < NP; ++np) {
                    uint32_t bh4[4], bl4[4];
                    ldmx4(bp + oBh + np * MT_STRIDE + ks * 32, bh4);
                    ldmx4(bp + oBh + WSZ + np * MT_STRIDE + ks * 32, bl4);
#pragma unroll
                    for (int mt = 0; mt < MT; ++mt)
#pragma unroll
                        for (int sub = 0; sub < 2; ++sub) {
                            int nt = np * 2 + sub, s = sub * 2;
                            mma_bf16(acc[mt][nt], ah[mt], bh4[s], bh4[s + 1]);
                            mma_bf16(acc[mt][nt], al[mt], bh4[s], bh4[s + 1]);
                            mma_bf16(acc[mt][nt], ah[mt], bl4[s], bl4[s + 1]);
                        }
                }
            } else {
                // B-outer (keeps regs bounded at MT=4)
                uint32_t bh[NP][4], bl[NP][4];
#pragma unroll
                for (int np = 0; np < NP; ++np) {
                    ldmx4(bp + oBh + np * MT_STRIDE + ks * 32, bh[np]);
                    ldmx4(bp + oBh + WSZ + np * MT_STRIDE + ks * 32, bl[np]);
                }
#pragma unroll
                for (int mt = 0; mt < MT; ++mt) {
                    uint32_t ah[4], al[4];
                    ldmx4(bp + oAh + mt * MT_STRIDE + ks * 32, ah);
                    ldmx4(bp + OFF_AL_ + oAh + mt * MT_STRIDE + ks * 32, al);
#pragma unroll
                    for (int np = 0; np < NP; ++np)
#pragma unroll
                        for (int sub = 0; sub < 2; ++sub) {
                            int nt = np * 2 + sub, s = sub * 2;
                            mma_bf16(acc[mt][nt], ah, bh[np][s], bh[np][s + 1]);
                            mma_bf16(acc[mt][nt], al, bh[np][s], bh[np][s + 1]);
                            mma_bf16(acc[mt][nt], ah, bl[np][s], bl[np][s + 1]);
                        }
                }
            }
        }

        // convert A(kc+1) -> buffer p^1
        if (kc < 15) convert(bq, kc + 1);
    }
    __syncthreads();   // smem free for epilogue reuse
}

// ---------------------------------------------------------------------------
// g1: GEMM1, M=128 (clip pair) x N=128, 2 CTAs/SM.  grid = (4 nc, 1280)
// ---------------------------------------------------------------------------
#define SMEM_G1 81920
__global__ void __launch_bounds__(256, 2)
g1_mma(const float* __restrict__ video, const float* __restrict__ bv1)
{
    extern __shared__ char sm[];
    const int tid = threadIdx.x, wid = tid >> 5, lane = tid & 31;
    const int wm = wid >> 2, wn = wid & 3;
    const int nc = blockIdx.x, bt0 = blockIdx.y * 2;
    const uint32_t aBase = smem_u32(sm);

    float acc[4][4][4];
#pragma unroll
    for (int a = 0; a < 4; ++a)
#pragma unroll
        for (int b = 0; b < 4; ++b)
#pragma unroll
            for (int c = 0; c < 4; ++c) acc[a][b][c] = 0.f;

    gemm_mainloop_t<2, 4>(acc, sm, aBase, video, nullptr,
                          g_W1h + (size_t)nc * 16 * CHUNK_ELEMS,
                          g_W1l + (size_t)nc * 16 * CHUNK_ELEMS,
                          nullptr, nullptr,
                          bt0, tid, lane, wm, wn);

    // stage relu(D + bias) into smem [128][132]  (67584 B <= 81920)
    float* stage = (float*)sm;
#pragma unroll
    for (int mt = 0; mt < 4; ++mt)
#pragma unroll
        for (int nt = 0; nt < 4; ++nt) {
            int r0 = wm * 64 + mt * 16 + (lane >> 2);
            int c0 = wn * 32 + nt * 8 + (lane & 3) * 2;
            float b0 = bv1[nc * 128 + c0], b1 = bv1[nc * 128 + c0 + 1];
            stage[r0 * 132 + c0]           = fmaxf(acc[mt][nt][0] + b0, 0.f);
            stage[r0 * 132 + c0 + 1]       = fmaxf(acc[mt][nt][1] + b1, 0.f);
            stage[(r0 + 8) * 132 + c0]     = fmaxf(acc[mt][nt][2] + b0, 0.f);
            stage[(r0 + 8) * 132 + c0 + 1] = fmaxf(acc[mt][nt][3] + b1, 0.f);
        }
    __syncthreads();

    {
        int clip = tid >> 7, col = tid & 127;
        float s = 0.f;
#pragma unroll
        for (int h = 0; h < HW_; ++h) s += stage[(clip * 64 + h) * 132 + col];
        int bt = bt0 + clip, c = nc * 128 + col;
        g_m1[(size_t)bt * VD_ + c] =
            g_aq1[(size_t)bt * VD_ + c] * s * (1.f / 49.f);
    }
}

// ---------------------------------------------------------------------------
// k3: channel-attention MLP (R11-proven coalesced variant)
// ---------------------------------------------------------------------------
__global__ void __launch_bounds__(256)
k3_catt(const float* __restrict__ bb, const float* __restrict__ bc)
{
    __shared__ __align__(16) float4 m1s4[16 * 128];
    __shared__ __align__(16) float t1s[16][HD_];
    const int tid = threadIdx.x;
    const int bt0 = blockIdx.x * 16;

    {
        const float4* src = (const float4*)(g_m1 + (size_t)bt0 * VD_);
        for (int i = tid; i < 16 * 128; i += 256) m1s4[i] = src[i];
    }
    __syncthreads();
    {
        const int j = tid;
        float acc[16];
#pragma unroll
        for (int i = 0; i < 16; ++i) acc[i] = 0.f;
        for (int k4 = 0; k4 < 128; ++k4) {
            float4 w = g_WbT4[k4 * 256 + j];
#pragma unroll
            for (int i = 0; i < 16; ++i) {
                float4 v = m1s4[i * 128 + k4];
                acc[i] += v.x * w.x + v.y * w.y + v.z * w.z + v.w * w.w;
            }
        }
        float bias = bb[j];
#pragma unroll
        for (int i = 0; i < 16; ++i) t1s[i][j] = fmaxf(acc[i] + bias, 0.f);
    }
    __syncthreads();
    {
        const int c0 = tid, c1 = tid + 256;
        float acc0[16], acc1[16];
#pragma unroll
        for (int i = 0; i < 16; ++i) { acc0[i] = 0.f; acc1[i] = 0.f; }
        for (int k4 = 0; k4 < 64; ++k4) {
            float4 w0 = g_WcT4[k4 * 512 + c0];
            float4 w1 = g_WcT4[k4 * 512 + c1];
#pragma unroll
            for (int i = 0; i < 16; ++i) {
                float4 v = *(const float4*)&t1s[i][k4 * 4];
                acc0[i] += v.x * w0.x + v.y * w0.y + v.z * w0.z + v.w * w0.w;
                acc1[i] += v.x * w1.x + v.y * w1.y + v.z * w1.z + v.w * w1.w;
            }
        }
        float b0 = bc[c0], b1 = bc[c1];
#pragma unroll
        for (int i = 0; i < 16; ++i) {
            float x0 = acc0[i] + b0, x1 = acc1[i] + b1;
            g_scale[(size_t)(bt0 + i) * VD_ + c0] = 1.f + 1.f / (1.f + expf(-x0));
            g_scale[(size_t)(bt0 + i) * VD_ + c1] = 1.f + 1.f / (1.f + expf(-x1));
        }
    }
}

// ---------------------------------------------------------------------------
// g2: GEMM2 (M=64, N=256) + relu x (aq2*Ws) + tanh/softmax + output
// grid = 2560 (byte-identical math to R13)
// ---------------------------------------------------------------------------
#define SMEM_G2 102400
__global__ void __launch_bounds__(256, 2)
g2_mma(const float* __restrict__ video, const float* __restrict__ bv2,
       const float* __restrict__ Ws, const float* __restrict__ bs,
       float* __restrict__ out)
{
    extern __shared__ char sm[];
    __shared__ float u_s[256];
    __shared__ __align__(16) float s_scale[512];
    __shared__ float part[64];
    __shared__ float swt[64];
    __shared__ float smx, sdn;
    const int tid = threadIdx.x, wid = tid >> 5, lane = tid & 31;
    const int wm = wid >> 2, wn = wid & 3;
    const int bt = blockIdx.x;
    const uint32_t aBase = smem_u32(sm);

    u_s[tid] = g_aq2[(size_t)bt * HD_ + tid] * Ws[tid];
    s_scale[tid]       = g_scale[(size_t)bt * VD_ + tid];
    s_scale[tid + 256] = g_scale[(size_t)bt * VD_ + tid + 256];
    if (tid < 64) part[tid] = 0.f;
    __syncthreads();

    float acc[2][8][4];
#pragma unroll
    for (int a = 0; a < 2; ++a)
#pragma unroll
        for (int b = 0; b < 8; ++b)
#pragma unroll
            for (int c = 0; c < 4; ++c) acc[a][b][c] = 0.f;

    gemm_mainloop_t<4, 2>(acc, sm, aBase, video, s_scale,
                          g_W2h, g_W2l,
                          g_W2h + (size_t)16 * CHUNK_ELEMS,
                          g_W2l + (size_t)16 * CHUNK_ELEMS,
                          bt, tid, lane, wm, wn);

#pragma unroll
    for (int mt = 0; mt < 2; ++mt) {
        int r0 = wm * 32 + mt * 16 + (lane >> 2);
        float s0 = 0.f, s1 = 0.f;
#pragma unroll
        for (int nt = 0; nt < 8; ++nt) {
            int c0 = wn * 64 + nt * 8 + (lane & 3) * 2;
            float b0 = bv2[c0], b1 = bv2[c0 + 1];
            float u0 = u_s[c0], u1 = u_s[c0 + 1];
            s0 += fmaxf(acc[mt][nt][0] + b0, 0.f) * u0
                + fmaxf(acc[mt][nt][1] + b1, 0.f) * u1;
            s1 += fmaxf(acc[mt][nt][2] + b0, 0.f) * u0
                + fmaxf(acc[mt][nt][3] + b1, 0.f) * u1;
        }
        s0 += __shfl_xor_sync(0xffffffffu, s0, 1);
        s0 += __shfl_xor_sync(0xffffffffu, s0, 2);
        s1 += __shfl_xor_sync(0xffffffffu, s1, 1);
        s1 += __shfl_xor_sync(0xffffffffu, s1, 2);
        if ((lane & 3) == 0) {
            atomicAdd(&part[r0], s0);
            atomicAdd(&part[r0 + 8], s1);
        }
    }
    __syncthreads();

    if (tid < HW_) swt[tid] = tanhf(part[tid] + bs[0]);
    __syncthreads();
    if (tid == 0) {
        float mx = -1e30f;
        for (int h = 0; h < HW_; ++h) mx = fmaxf(mx, swt[h]);
        float den = 0.f;
        for (int h = 0; h < HW_; ++h) den += expf(swt[h] - mx);
        smx = mx; sdn = den;
    }
    __syncthreads();
    if (tid < HW_) swt[tid] = expf(swt[tid] - smx) / sdn;
    __syncthreads();

    for (int c = tid; c < VD_; c += 256) {
        float a = 0.f;
#pragma unroll 7
        for (int h = 0; h < HW_; ++h)
            a += swt[h] * video[((size_t)bt * HW_ + h) * VD_ + c];
        out[(size_t)bt * VD_ + c] = a * s_scale[c];
    }
}

// ---------------------------------------------------------------------------
// Launch
// ---------------------------------------------------------------------------
extern "C" void kernel_launch(void* const* d_in, const int* in_sizes, int n_in,
                              void* d_out, int out_size)
{
    const float* video = (const float*)d_in[0];
    const float* audio = (const float*)d_in[1];
    const float* Wv1   = (const float*)d_in[2];
    const float* bv1   = (const float*)d_in[3];
    const float* Wa1   = (const float*)d_in[4];
    const float* ba1   = (const float*)d_in[5];
    const float* Wb    = (const float*)d_in[6];
    const float* bb    = (const float*)d_in[7];
    const float* Wc    = (const float*)d_in[8];
    const float* bc    = (const float*)d_in[9];
    const float* Wv2   = (const float*)d_in[10];
    const float* bv2   = (const float*)d_in[11];
    const float* Wa2   = (const float*)d_in[12];
    const float* ba2   = (const float*)d_in[13];
    const float* Ws    = (const float*)d_in[14];
    const float* bs    = (const float*)d_in[15];
    float* out = (float*)d_out;

    cudaFuncSetAttribute(g1_mma, cudaFuncAttributeMaxDynamicSharedMemorySize, SMEM_G1);
    cudaFuncSetAttribute(g2_mma, cudaFuncAttributeMaxDynamicSharedMemorySize, SMEM_G2);

    k0_wconv<<<1536, 256>>>(Wv1, Wv2);
    kt_trans<<<256, 256>>>(Wb, Wc);
    k1_audio<<<BT_ / 32, 256>>>(audio, Wa1, ba1, Wa2, ba2);
    g1_mma<<<dim3(4, BT_ / 2), 256, SMEM_G1>>>(video, bv1);
    k3_catt<<<BT_ / 16, 256>>>(bb, bc);
    g2_mma<<<BT_, 256, SMEM_G2>>>(video, bv2, Ws, bs, out);
}

// round 16
// speedup vs baseline: 1.1175x; 1.1175x over previous
#include <cuda_runtime.h>
#include <cuda_bf16.h>
#include <cstdint>

#define B_   256
#define T_   10
#define BT_  2560
#define HW_  49
#define VD_  512
#define AD_  128
#define HD_  256

// ---------------------------------------------------------------------------
// Scratch (__device__ globals — allocation-free)
// ---------------------------------------------------------------------------
__device__ float g_aq1[BT_ * VD_];
__device__ float g_aq2[BT_ * HD_];
__device__ float g_m1 [BT_ * VD_];
__device__ float g_scale[BT_ * VD_];

// Pre-split bf16 weight images, K=32 chunks, unpadded 64B rows:
// [n_chunk][k_chunk(16)][128 n-rows][32 k]
__device__ __align__(16) __nv_bfloat16 g_W1h[4 * 16 * 128 * 32];
__device__ __align__(16) __nv_bfloat16 g_W1l[4 * 16 * 128 * 32];
__device__ __align__(16) __nv_bfloat16 g_W2h[2 * 16 * 128 * 32];
__device__ __align__(16) __nv_bfloat16 g_W2l[2 * 16 * 128 * 32];

// Transposed packed fp32 weights for k3
__device__ __align__(16) float4 g_WbT4[128 * 256];
__device__ __align__(16) float4 g_WcT4[64 * 512];

#define CHUNK_ELEMS (128 * 32)           // 4096 bf16 = 8192 B per image chunk
#define ROWB 80                          // smem row stride (32 bf16 + 16B pad)
#define MT_STRIDE (16 * ROWB)            // 1280

// ---------------------------------------------------------------------------
// Helpers (plain sm_103-safe PTX only)
// ---------------------------------------------------------------------------
__device__ __forceinline__ uint32_t smem_u32(const void* p) {
    uint32_t a;
    asm("{ .reg .u64 t; cvta.to.shared.u64 t, %1; cvt.u32.u64 %0, t; }"
        : "=r"(a) : "l"(p));
    return a;
}
__device__ __forceinline__ void ldmx4(uint32_t addr, uint32_t r[4]) {
    asm volatile("ldmatrix.sync.aligned.m8n8.x4.shared.b16 {%0,%1,%2,%3}, [%4];"
                 : "=r"(r[0]), "=r"(r[1]), "=r"(r[2]), "=r"(r[3]) : "r"(addr));
}
__device__ __forceinline__ void mma_bf16(float d[4], const uint32_t a[4],
                                         uint32_t b0, uint32_t b1) {
    asm volatile(
        "mma.sync.aligned.m16n8k16.row.col.f32.bf16.bf16.f32 "
        "{%0,%1,%2,%3},{%4,%5,%6,%7},{%8,%9},{%0,%1,%2,%3};"
        : "+f"(d[0]), "+f"(d[1]), "+f"(d[2]), "+f"(d[3])
        : "r"(a[0]), "r"(a[1]), "r"(a[2]), "r"(a[3]), "r"(b0), "r"(b1));
}
__device__ __forceinline__ void cp16(uint32_t dst, const void* src) {
    asm volatile("cp.async.cg.shared.global [%0], [%1], 16;" :: "r"(dst), "l"(src));
}
#define CP_COMMIT() asm volatile("cp.async.commit_group;" ::: "memory")
#define CP_WAIT0()  asm volatile("cp.async.wait_group 0;" ::: "memory")

__device__ __forceinline__ void split_store(char* Ah, char* Al, int r, int q,
                                            float x0, float x1, float x2, float x3) {
    __nv_bfloat16 h0 = __float2bfloat16(x0), h1 = __float2bfloat16(x1);
    __nv_bfloat16 h2 = __float2bfloat16(x2), h3 = __float2bfloat16(x3);
    __nv_bfloat16 l0 = __float2bfloat16(x0 - __bfloat162float(h0));
    __nv_bfloat16 l1 = __float2bfloat16(x1 - __bfloat162float(h1));
    __nv_bfloat16 l2 = __float2bfloat16(x2 - __bfloat162float(h2));
    __nv_bfloat16 l3 = __float2bfloat16(x3 - __bfloat162float(h3));
    __nv_bfloat162 p;
    char* dh = Ah + r * ROWB + q * 8;
    char* dl = Al + r * ROWB + q * 8;
    p.x = h0; p.y = h1; *(__nv_bfloat162*)dh = p;
    p.x = h2; p.y = h3; *(__nv_bfloat162*)(dh + 4) = p;
    p.x = l0; p.y = l1; *(__nv_bfloat162*)dl = p;
    p.x = l2; p.y = l3; *(__nv_bfloat162*)(dl + 4) = p;
}

// ---------------------------------------------------------------------------
// k0 / kt / k1: unchanged proven pre-pass kernels
// ---------------------------------------------------------------------------
__global__ void __launch_bounds__(256)
k0_wconv(const float* __restrict__ Wv1, const float* __restrict__ Wv2)
{
    int idx = blockIdx.x * 256 + threadIdx.x;
    if (idx < 512 * 512) {
        int c = idx >> 9, k = idx & 511;
        float v = Wv1[idx];
        __nv_bfloat16 h = __float2bfloat16(v);
        __nv_bfloat16 l = __float2bfloat16(v - __bfloat162float(h));
        int nc = c >> 7, nl = c & 127, kc = k >> 5, kk = k & 31;
        size_t d = ((size_t)(nc * 16 + kc) * 128 + nl) * 32 + kk;
        g_W1h[d] = h; g_W1l[d] = l;
    } else if (idx < 512 * 512 + 256 * 512) {
        int e = idx - 512 * 512;
        int j = e >> 9, k = e & 511;
        float v = Wv2[e];
        __nv_bfloat16 h = __float2bfloat16(v);
        __nv_bfloat16 l = __float2bfloat16(v - __bfloat162float(h));
        int nc = j >> 7, nl = j & 127, kc = k >> 5, kk = k & 31;
        size_t d = ((size_t)(nc * 16 + kc) * 128 + nl) * 32 + kk;
        g_W2h[d] = h; g_W2l[d] = l;
    }
}

__global__ void __launch_bounds__(256)
kt_trans(const float* __restrict__ Wb, const float* __restrict__ Wc)
{
    int idx = blockIdx.x * 256 + threadIdx.x;
    if (idx < 128 * 256) {
        int k4 = idx >> 8, j = idx & 255;
        const float* s = Wb + (size_t)j * VD_ + k4 * 4;
        g_WbT4[idx] = make_float4(s[0], s[1], s[2], s[3]);
    } else if (idx < 128 * 256 + 64 * 512) {
        int e = idx - 128 * 256;
        int k4 = e >> 9, c = e & 511;
        const float* s = Wc + (size_t)c * HD_ + k4 * 4;
        g_WcT4[e] = make_float4(s[0], s[1], s[2], s[3]);
    }
}

__global__ void __launch_bounds__(256)
k1_audio(const float* __restrict__ audio,
         const float* __restrict__ Wa1, const float* __restrict__ ba1,
         const float* __restrict__ Wa2, const float* __restrict__ ba2)
{
    __shared__ __align__(16) float af[32][AD_];
    const int tid = threadIdx.x;
    const int bt0 = blockIdx.x * 32;

    for (int idx = tid; idx < 32 * AD_; idx += 256) {
        int i = idx >> 7, k = idx & 127;
        int bt = bt0 + i;
        int b = bt / T_, t = bt - b * T_;
        af[i][k] = audio[((size_t)t * B_ + b) * AD_ + k];
    }
    __syncthreads();

    for (int c = tid; c < VD_; c += 256) {
        const float4* w4 = (const float4*)(Wa1 + (size_t)c * AD_);
        float acc[32];
#pragma unroll
        for (int i = 0; i < 32; ++i) acc[i] = 0.f;
        for (int k4 = 0; k4 < AD_ / 4; ++k4) {
            float4 w = w4[k4];
#pragma unroll
            for (int i = 0; i < 32; ++i) {
                float4 v = *(const float4*)&af[i][k4 * 4];
                acc[i] += v.x * w.x + v.y * w.y + v.z * w.z + v.w * w.w;
            }
        }
        float bias = ba1[c];
#pragma unroll
        for (int i = 0; i < 32; ++i)
            g_aq1[(size_t)(bt0 + i) * VD_ + c] = fmaxf(acc[i] + bias, 0.f);
    }
    {
        int j = tid;
        const float4* w4 = (const float4*)(Wa2 + (size_t)j * AD_);
        float acc[32];
#pragma unroll
        for (int i = 0; i < 32; ++i) acc[i] = 0.f;
        for (int k4 = 0; k4 < AD_ / 4; ++k4) {
            float4 w = w4[k4];
#pragma unroll
            for (int i = 0; i < 32; ++i) {
                float4 v = *(const float4*)&af[i][k4 * 4];
                acc[i] += v.x * w.x + v.y * w.y + v.z * w.z + v.w * w.w;
            }
        }
        float bias = ba2[j];
#pragma unroll
        for (int i = 0; i < 32; ++i)
            g_aq2[(size_t)(bt0 + i) * HD_ + j] = fmaxf(acc[i] + bias, 0.f);
    }
}

// ===========================================================================
// g1: GEMM1 with M=112 tile (2 clips: rows 0-48, 56-104; pads 49-55/105-111)
//     N=128. 8 warps: each owns a 16-wide N slice x all 7 M tiles.
//     Double-buffered K=32 chunks, A reg-prefetch (R13 schedule).
// SMEM/buffer: A_h@0(8960) A_l@8960 W_h@17920(10240) W_l@28160(10240)
// ===========================================================================
#define G1_AL   8960
#define G1_WH   17920
#define G1_WL   28160
#define G1_BUF  38400
#define SMEM_G1 76800

__global__ void __launch_bounds__(256, 2)
g1_mma(const float* __restrict__ video, const float* __restrict__ bv1)
{
    extern __shared__ char sm[];
    const int tid = threadIdx.x, wid = tid >> 5, lane = tid & 31;
    const int nc = blockIdx.x, bt0 = blockIdx.y * 2;
    const uint32_t aBase = smem_u32(sm);

    float acc[7][2][4];
#pragma unroll
    for (int a = 0; a < 7; ++a)
#pragma unroll
        for (int b = 0; b < 2; ++b)
#pragma unroll
            for (int c = 0; c < 4; ++c) acc[a][b][c] = 0.f;

    // zero pad rows (49-55, 105-111) in both buffers, hi+lo: 14 rows x 16 words
    if (tid < 224) {
        int rr = tid >> 4, w = (tid & 15) * 4;
        int r = (rr < 7) ? (49 + rr) : (98 + rr);
#pragma unroll
        for (int b = 0; b < 2; ++b) {
            *(uint32_t*)(sm + b * G1_BUF + r * ROWB + w) = 0u;
            *(uint32_t*)(sm + b * G1_BUF + G1_AL + r * ROWB + w) = 0u;
        }
    }

    // A conversion: 784 float4 items (2 clips x 49 rows x 8 q) over 256 threads
    // slots 0-2 always valid (<=767), slot 3 valid for tid<16
    int pr_[4], q_[4];
    const float* vr_[4];
#pragma unroll
    for (int s = 0; s < 4; ++s) {
        int i = tid + s * 256;
        if (i >= 784) i = 0;
        int r = i >> 3, q = i & 7;
        int clip = (r >= 49);
        int h = r - clip * 49;
        pr_[s] = r + clip * 7;            // clip1 at phys rows 56..104
        q_[s] = q;
        vr_[s] = video + ((size_t)(bt0 + clip) * HW_ + h) * VD_ + q * 4;
    }
    const bool has3 = (tid < 16);

    // per-lane ldmatrix offsets (within a buffer)
    const uint32_t oA = (uint32_t)((lane & 15) * ROWB + ((lane >> 4) & 1) * 16);
    const uint32_t oB = G1_WH
                      + (uint32_t)((wid * 16 + (lane & 7) + ((lane >> 4) & 1) * 8) * ROWB
                      + ((lane >> 3) & 1) * 16);

    const __nv_bfloat16* wH = g_W1h + (size_t)nc * 16 * CHUNK_ELEMS;
    const __nv_bfloat16* wL = g_W1l + (size_t)nc * 16 * CHUNK_ELEMS;

    auto issue_w = [&](uint32_t dstBase, int kc) {
        const char* sH = (const char*)(wH + (size_t)kc * CHUNK_ELEMS);
        const char* sL = (const char*)(wL + (size_t)kc * CHUNK_ELEMS);
#pragma unroll
        for (int i = tid; i < 512; i += 256) {
            int r = i >> 2, qq = i & 3;
            uint32_t dof = (uint32_t)(r * ROWB + qq * 16);
            int sof = r * 64 + qq * 16;
            cp16(dstBase + G1_WH + dof, sH + sof);
            cp16(dstBase + G1_WL + dof, sL + sof);
        }
    };

    // prologue: chunk 0 -> buf0
    {
#pragma unroll
        for (int s = 0; s < 3; ++s) {
            float4 v = *(const float4*)vr_[s];
            split_store(sm, sm + G1_AL, pr_[s], q_[s], v.x, v.y, v.z, v.w);
        }
        if (has3) {
            float4 v = *(const float4*)vr_[3];
            split_store(sm, sm + G1_AL, pr_[3], q_[3], v.x, v.y, v.z, v.w);
        }
        issue_w(aBase, 0);
        CP_COMMIT();
    }

    for (int kc = 0; kc < 16; ++kc) {
        const int p = kc & 1;
        const uint32_t bp = aBase + p * G1_BUF;
        char* bq = sm + (p ^ 1) * G1_BUF;
        CP_WAIT0();
        __syncthreads();

        float4 pv0, pv1, pv2;
        if (kc < 15) {
            issue_w(aBase + (p ^ 1) * G1_BUF, kc + 1);
            CP_COMMIT();
            pv0 = *(const float4*)(vr_[0] + (kc + 1) * 32);
            pv1 = *(const float4*)(vr_[1] + (kc + 1) * 32);
            pv2 = *(const float4*)(vr_[2] + (kc + 1) * 32);
        }

        // MMA on chunk kc
#pragma unroll
        for (int ks = 0; ks < 2; ++ks) {
            uint32_t bh4[4], bl4[4];
            ldmx4(bp + oB + ks * 32, bh4);
            ldmx4(bp + oB + (G1_WL - G1_WH) + ks * 32, bl4);
#pragma unroll
            for (int mt = 0; mt < 7; ++mt) {
                uint32_t ah[4], al[4];
                ldmx4(bp + oA + mt * MT_STRIDE + ks * 32, ah);
                ldmx4(bp + G1_AL + oA + mt * MT_STRIDE + ks * 32, al);
#pragma unroll
                for (int sub = 0; sub < 2; ++sub) {
                    int s = sub * 2;
                    mma_bf16(acc[mt][sub], ah, bh4[s], bh4[s + 1]);
                    mma_bf16(acc[mt][sub], al, bh4[s], bh4[s + 1]);
                    mma_bf16(acc[mt][sub], ah, bl4[s], bl4[s + 1]);
                }
            }
        }

        // convert A(kc+1) -> buffer p^1 (slots 0-2 from regs, slot 3 direct)
        if (kc < 15) {
            split_store(bq, bq + G1_AL, pr_[0], q_[0], pv0.x, pv0.y, pv0.z, pv0.w);
            split_store(bq, bq + G1_AL, pr_[1], q_[1], pv1.x, pv1.y, pv1.z, pv1.w);
            split_store(bq, bq + G1_AL, pr_[2], q_[2], pv2.x, pv2.y, pv2.z, pv2.w);
            if (has3) {
                float4 v = *(const float4*)(vr_[3] + (kc + 1) * 32);
                split_store(bq, bq + G1_AL, pr_[3], q_[3], v.x, v.y, v.z, v.w);
            }
        }
    }
    __syncthreads();   // smem free for epilogue reuse

    // stage relu(D + bias) into smem [112][132]  (59136 B <= 76800)
    float* stage = (float*)sm;
#pragma unroll
    for (int mt = 0; mt < 7; ++mt)
#pragma unroll
        for (int sub = 0; sub < 2; ++sub) {
            int r0 = mt * 16 + (lane >> 2);
            int c0 = wid * 16 + sub * 8 + (lane & 3) * 2;
            float b0 = bv1[nc * 128 + c0], b1 = bv1[nc * 128 + c0 + 1];
            stage[r0 * 132 + c0]           = fmaxf(acc[mt][sub][0] + b0, 0.f);
            stage[r0 * 132 + c0 + 1]       = fmaxf(acc[mt][sub][1] + b1, 0.f);
            stage[(r0 + 8) * 132 + c0]     = fmaxf(acc[mt][sub][2] + b0, 0.f);
            stage[(r0 + 8) * 132 + c0 + 1] = fmaxf(acc[mt][sub][3] + b1, 0.f);
        }
    __syncthreads();

    {
        int clip = tid >> 7, col = tid & 127;
        float s = 0.f;
#pragma unroll
        for (int h = 0; h < HW_; ++h) s += stage[(clip * 56 + h) * 132 + col];
        int bt = bt0 + clip, c = nc * 128 + col;
        g_m1[(size_t)bt * VD_ + c] =
            g_aq1[(size_t)bt * VD_ + c] * s * (1.f / 49.f);
    }
}

// ---------------------------------------------------------------------------
// k3: channel-attention MLP (R11-proven coalesced variant)
// ---------------------------------------------------------------------------
__global__ void __launch_bounds__(256)
k3_catt(const float* __restrict__ bb, const float* __restrict__ bc)
{
    __shared__ __align__(16) float4 m1s4[16 * 128];
    __shared__ __align__(16) float t1s[16][HD_];
    const int tid = threadIdx.x;
    const int bt0 = blockIdx.x * 16;

    {
        const float4* src = (const float4*)(g_m1 + (size_t)bt0 * VD_);
        for (int i = tid; i < 16 * 128; i += 256) m1s4[i] = src[i];
    }
    __syncthreads();
    {
        const int j = tid;
        float acc[16];
#pragma unroll
        for (int i = 0; i < 16; ++i) acc[i] = 0.f;
        for (int k4 = 0; k4 < 128; ++k4) {
            float4 w = g_WbT4[k4 * 256 + j];
#pragma unroll
            for (int i = 0; i < 16; ++i) {
                float4 v = m1s4[i * 128 + k4];
                acc[i] += v.x * w.x + v.y * w.y + v.z * w.z + v.w * w.w;
            }
        }
        float bias = bb[j];
#pragma unroll
        for (int i = 0; i < 16; ++i) t1s[i][j] = fmaxf(acc[i] + bias, 0.f);
    }
    __syncthreads();
    {
        const int c0 = tid, c1 = tid + 256;
        float acc0[16], acc1[16];
#pragma unroll
        for (int i = 0; i < 16; ++i) { acc0[i] = 0.f; acc1[i] = 0.f; }
        for (int k4 = 0; k4 < 64; ++k4) {
            float4 w0 = g_WcT4[k4 * 512 + c0];
            float4 w1 = g_WcT4[k4 * 512 + c1];
#pragma unroll
            for (int i = 0; i < 16; ++i) {
                float4 v = *(const float4*)&t1s[i][k4 * 4];
                acc0[i] += v.x * w0.x + v.y * w0.y + v.z * w0.z + v.w * w0.w;
                acc1[i] += v.x * w1.x + v.y * w1.y + v.z * w1.z + v.w * w1.w;
            }
        }
        float b0 = bc[c0], b1 = bc[c1];
#pragma unroll
        for (int i = 0; i < 16; ++i) {
            float x0 = acc0[i] + b0, x1 = acc1[i] + b1;
            g_scale[(size_t)(bt0 + i) * VD_ + c0] = 1.f + 1.f / (1.f + expf(-x0));
            g_scale[(size_t)(bt0 + i) * VD_ + c1] = 1.f + 1.f / (1.f + expf(-x1));
        }
    }
}

// ===========================================================================
// g2: exact R13 path — M=64 (one clip), N=256, double-buffered K=32,
//     A reg-prefetch, fused relu/(aq2*Ws)/tanh/softmax/output epilogue.
// SMEM/buffer: A_h@0(5120) A_l@5120 W_h@10240(20480) W_l@30720(20480)
// ===========================================================================
#define G2_AL   5120
#define G2_WH   10240
#define G2_WL   30720
#define G2_BUF  51200
#define SMEM_G2 102400

__global__ void __launch_bounds__(256, 2)
g2_mma(const float* __restrict__ video, const float* __restrict__ bv2,
       const float* __restrict__ Ws, const float* __restrict__ bs,
       float* __restrict__ out)
{
    extern __shared__ char sm[];
    __shared__ float u_s[256];
    __shared__ __align__(16) float s_scale[512];
    __shared__ float part[64];
    __shared__ float swt[64];
    __shared__ float smx, sdn;
    const int tid = threadIdx.x, wid = tid >> 5, lane = tid & 31;
    const int wm = wid >> 2, wn = wid & 3;
    const int bt = blockIdx.x;
    const uint32_t aBase = smem_u32(sm);

    u_s[tid] = g_aq2[(size_t)bt * HD_ + tid] * Ws[tid];
    s_scale[tid]       = g_scale[(size_t)bt * VD_ + tid];
    s_scale[tid + 256] = g_scale[(size_t)bt * VD_ + tid + 256];
    if (tid < 64) part[tid] = 0.f;
    __syncthreads();

    float acc[2][8][4];
#pragma unroll
    for (int a = 0; a < 2; ++a)
#pragma unroll
        for (int b = 0; b < 8; ++b)
#pragma unroll
            for (int c = 0; c < 4; ++c) acc[a][b][c] = 0.f;

    // zero pad rows 49..63 in both buffers, hi+lo
    if (tid < 240) {
        int r = 49 + tid / 16, w = (tid & 15) * 4;
#pragma unroll
        for (int b = 0; b < 2; ++b) {
            *(uint32_t*)(sm + b * G2_BUF + r * ROWB + w) = 0u;
            *(uint32_t*)(sm + b * G2_BUF + G2_AL + r * ROWB + w) = 0u;
        }
    }

    // A conversion: 392 items over 256 threads (2 slots)
    const int i0 = tid, i1 = tid + 256;
    const int r0_ = i0 >> 3, q0 = i0 & 7;
    const int r1_ = i1 >> 3, q1 = i1 & 7;
    const bool has1 = (i1 < 392);
    const float* vrow0 = video + ((size_t)bt * HW_ + r0_) * VD_ + q0 * 4;
    const float* vrow1 = video + ((size_t)bt * HW_ + (has1 ? r1_ : 0)) * VD_ + q1 * 4;

    // per-lane ldmatrix offsets (buffer-relative)
    const uint32_t oAh = (uint32_t)((wm * 32 + (lane & 15)) * ROWB
                        + ((lane >> 4) & 1) * 16);
    const uint32_t oBh = G2_WH
                        + (uint32_t)((wn * 64 + (lane & 7) + ((lane >> 4) & 1) * 8) * ROWB
                        + ((lane >> 3) & 1) * 16);

    auto issue_w = [&](uint32_t dstBase, int kc) {
        const char* sH0 = (const char*)(g_W2h + (size_t)kc * CHUNK_ELEMS);
        const char* sL0 = (const char*)(g_W2l + (size_t)kc * CHUNK_ELEMS);
        const char* sH1 = (const char*)(g_W2h + (size_t)(16 + kc) * CHUNK_ELEMS);
        const char* sL1 = (const char*)(g_W2l + (size_t)(16 + kc) * CHUNK_ELEMS);
#pragma unroll
        for (int i = tid; i < 512; i += 256) {
            int r = i >> 2, qq = i & 3;
            uint32_t dof = (uint32_t)(r * ROWB + qq * 16);
            int sof = r * 64 + qq * 16;
            cp16(dstBase + G2_WH + dof,         sH0 + sof);
            cp16(dstBase + G2_WH + 10240 + dof, sH1 + sof);
            cp16(dstBase + G2_WL + dof,         sL0 + sof);
            cp16(dstBase + G2_WL + 10240 + dof, sL1 + sof);
        }
    };

    // prologue: chunk 0 -> buf0
    {
        float4 v0 = *(const float4*)vrow0;
        float4 v1 = has1 ? *(const float4*)vrow1 : make_float4(0.f, 0.f, 0.f, 0.f);
        {
            float4 s0 = *(const float4*)(s_scale + q0 * 4);
            v0.x *= s0.x; v0.y *= s0.y; v0.z *= s0.z; v0.w *= s0.w;
            if (has1) {
                float4 s1 = *(const float4*)(s_scale + q1 * 4);
                v1.x *= s1.x; v1.y *= s1.y; v1.z *= s1.z; v1.w *= s1.w;
            }
        }
        split_store(sm, sm + G2_AL, r0_, q0, v0.x, v0.y, v0.z, v0.w);
        if (has1) split_store(sm, sm + G2_AL, r1_, q1, v1.x, v1.y, v1.z, v1.w);
        issue_w(aBase, 0);
        CP_COMMIT();
    }

    for (int kc = 0; kc < 16; ++kc) {
        const int p = kc & 1;
        const uint32_t bp = aBase + p * G2_BUF;
        char* bq = sm + (p ^ 1) * G2_BUF;
        CP_WAIT0();
        __syncthreads();

        float4 v0, v1;
        if (kc < 15) {
            issue_w(aBase + (p ^ 1) * G2_BUF, kc + 1);
            CP_COMMIT();
            v0 = *(const float4*)(vrow0 + (kc + 1) * 32);
            if (has1) v1 = *(const float4*)(vrow1 + (kc + 1) * 32);
        }

#pragma unroll
        for (int ks = 0; ks < 2; ++ks) {
            uint32_t ah[2][4], al[2][4];
#pragma unroll
            for (int mt = 0; mt < 2; ++mt) {
                ldmx4(bp + oAh + mt * MT_STRIDE + ks * 32, ah[mt]);
                ldmx4(bp + G2_AL + oAh + mt * MT_STRIDE + ks * 32, al[mt]);
            }
#pragma unroll
            for (int np = 0; np < 4; ++np) {
                uint32_t bh4[4], bl4[4];
                ldmx4(bp + oBh + np * MT_STRIDE + ks * 32, bh4);
                ldmx4(bp + oBh + (G2_WL - G2_WH) + np * MT_STRIDE + ks * 32, bl4);
#pragma unroll
                for (int mt = 0; mt < 2; ++mt)
#pragma unroll
                    for (int sub = 0; sub < 2; ++sub) {
                        int nt = np * 2 + sub, s = sub * 2;
                        mma_bf16(acc[mt][nt], ah[mt], bh4[s], bh4[s + 1]);
                        mma_bf16(acc[mt][nt], al[mt], bh4[s], bh4[s + 1]);
                        mma_bf16(acc[mt][nt], ah[mt], bl4[s], bl4[s + 1]);
                    }
            }
        }

        if (kc < 15) {
            {
                float4 s0 = *(const float4*)(s_scale + (kc + 1) * 32 + q0 * 4);
                v0.x *= s0.x; v0.y *= s0.y; v0.z *= s0.z; v0.w *= s0.w;
                if (has1) {
                    float4 s1 = *(const float4*)(s_scale + (kc + 1) * 32 + q1 * 4);
                    v1.x *= s1.x; v1.y *= s1.y; v1.z *= s1.z; v1.w *= s1.w;
                }
            }
            split_store(bq, bq + G2_AL, r0_, q0, v0.x, v0.y, v0.z, v0.w);
            if (has1) split_store(bq, bq + G2_AL, r1_, q1, v1.x, v1.y, v1.z, v1.w);
        }
    }
    __syncthreads();

    // row sums: sum_j relu(D + bv2[j]) * u[j]
#pragma unroll
    for (int mt = 0; mt < 2; ++mt) {
        int r0 = wm * 32 + mt * 16 + (lane >> 2);
        float s0 = 0.f, s1 = 0.f;
#pragma unroll
        for (int nt = 0; nt < 8; ++nt) {
            int c0 = wn * 64 + nt * 8 + (lane & 3) * 2;
            float b0 = bv2[c0], b1 = bv2[c0 + 1];
            float u0 = u_s[c0], u1 = u_s[c0 + 1];
            s0 += fmaxf(acc[mt][nt][0] + b0, 0.f) * u0
                + fmaxf(acc[mt][nt][1] + b1, 0.f) * u1;
            s1 += fmaxf(acc[mt][nt][2] + b0, 0.f) * u0
                + fmaxf(acc[mt][nt][3] + b1, 0.f) * u1;
        }
        s0 += __shfl_xor_sync(0xffffffffu, s0, 1);
        s0 += __shfl_xor_sync(0xffffffffu, s0, 2);
        s1 += __shfl_xor_sync(0xffffffffu, s1, 1);
        s1 += __shfl_xor_sync(0xffffffffu, s1, 2);
        if ((lane & 3) == 0) {
            atomicAdd(&part[r0], s0);
            atomicAdd(&part[r0 + 8], s1);
        }
    }
    __syncthreads();

    if (tid < HW_) swt[tid] = tanhf(part[tid] + bs[0]);
    __syncthreads();
    if (tid == 0) {
        float mx = -1e30f;
        for (int h = 0; h < HW_; ++h) mx = fmaxf(mx, swt[h]);
        float den = 0.f;
        for (int h = 0; h < HW_; ++h) den += expf(swt[h] - mx);
        smx = mx; sdn = den;
    }
    __syncthreads();
    if (tid < HW_) swt[tid] = expf(swt[tid] - smx) / sdn;
    __syncthreads();

    for (int c = tid; c < VD_; c += 256) {
        float a = 0.f;
#pragma unroll 7
        for (int h = 0; h < HW_; ++h)
            a += swt[h] * video[((size_t)bt * HW_ + h) * VD_ + c];
        out[(size_t)bt * VD_ + c] = a * s_scale[c];
    }
}

// ---------------------------------------------------------------------------
// Launch
// ---------------------------------------------------------------------------
extern "C" void kernel_launch(void* const* d_in, const int* in_sizes, int n_in,
                              void* d_out, int out_size)
{
    const float* video = (const float*)d_in[0];
    const float* audio = (const float*)d_in[1];
    const float* Wv1   = (const float*)d_in[2];
    const float* bv1   = (const float*)d_in[3];
    const float* Wa1   = (const float*)d_in[4];
    const float* ba1   = (const float*)d_in[5];
    const float* Wb    = (const float*)d_in[6];
    const float* bb    = (const float*)d_in[7];
    const float* Wc    = (const float*)d_in[8];
    const float* bc    = (const float*)d_in[9];
    const float* Wv2   = (const float*)d_in[10];
    const float* bv2   = (const float*)d_in[11];
    const float* Wa2   = (const float*)d_in[12];
    const float* ba2   = (const float*)d_in[13];
    const float* Ws    = (const float*)d_in[14];
    const float* bs    = (const float*)d_in[15];
    float* out = (float*)d_out;

    cudaFuncSetAttribute(g1_mma, cudaFuncAttributeMaxDynamicSharedMemorySize, SMEM_G1);
    cudaFuncSetAttribute(g2_mma, cudaFuncAttributeMaxDynamicSharedMemorySize, SMEM_G2);

    k0_wconv<<<1536, 256>>>(Wv1, Wv2);
    kt_trans<<<256, 256>>>(Wb, Wc);
    k1_audio<<<BT_ / 32, 256>>>(audio, Wa1, ba1, Wa2, ba2);
    g1_mma<<<dim3(4, BT_ / 2), 256, SMEM_G1>>>(video, bv1);
    k3_catt<<<BT_ / 16, 256>>>(bb, bc);
    g2_mma<<<BT_, 256, SMEM_G2>>>(video, bv2, Ws, bs, out);
}

// round 17
// speedup vs baseline: 1.1178x; 1.0002x over previous
#include <cuda_runtime.h>
#include <cuda_bf16.h>
#include <cstdint>

#define B_   256
#define T_   10
#define BT_  2560
#define HW_  49
#define VD_  512
#define AD_  128
#define HD_  256

// ---------------------------------------------------------------------------
// Scratch (__device__ globals — allocation-free)
// ---------------------------------------------------------------------------
__device__ float g_aq1[BT_ * VD_];
__device__ float g_aq2[BT_ * HD_];
__device__ float g_m1 [BT_ * VD_];
__device__ float g_scale[BT_ * VD_];

// Pre-split bf16 weight images, K=32 chunks, unpadded 64B rows:
// [n_chunk][k_chunk(16)][128 n-rows][32 k]
__device__ __align__(16) __nv_bfloat16 g_W1h[4 * 16 * 128 * 32];
__device__ __align__(16) __nv_bfloat16 g_W1l[4 * 16 * 128 * 32];
__device__ __align__(16) __nv_bfloat16 g_W2h[2 * 16 * 128 * 32];
__device__ __align__(16) __nv_bfloat16 g_W2l[2 * 16 * 128 * 32];

// Transposed packed fp32 weights for k3
__device__ __align__(16) float4 g_WbT4[128 * 256];
__device__ __align__(16) float4 g_WcT4[64 * 512];

#define CHUNK_ELEMS (128 * 32)           // 4096 bf16 = 8192 B per image chunk
#define ROWB 80                          // smem row stride (32 bf16 + 16B pad)
#define MT_STRIDE (16 * ROWB)            // 1280

// ---------------------------------------------------------------------------
// Helpers (plain sm_103-safe PTX only)
// ---------------------------------------------------------------------------
__device__ __forceinline__ uint32_t smem_u32(const void* p) {
    uint32_t a;
    asm("{ .reg .u64 t; cvta.to.shared.u64 t, %1; cvt.u32.u64 %0, t; }"
        : "=r"(a) : "l"(p));
    return a;
}
__device__ __forceinline__ void ldmx4(uint32_t addr, uint32_t r[4]) {
    asm volatile("ldmatrix.sync.aligned.m8n8.x4.shared.b16 {%0,%1,%2,%3}, [%4];"
                 : "=r"(r[0]), "=r"(r[1]), "=r"(r[2]), "=r"(r[3]) : "r"(addr));
}
__device__ __forceinline__ void mma_bf16(float d[4], const uint32_t a[4],
                                         uint32_t b0, uint32_t b1) {
    asm volatile(
        "mma.sync.aligned.m16n8k16.row.col.f32.bf16.bf16.f32 "
        "{%0,%1,%2,%3},{%4,%5,%6,%7},{%8,%9},{%0,%1,%2,%3};"
        : "+f"(d[0]), "+f"(d[1]), "+f"(d[2]), "+f"(d[3])
        : "r"(a[0]), "r"(a[1]), "r"(a[2]), "r"(a[3]), "r"(b0), "r"(b1));
}
__device__ __forceinline__ void cp16(uint32_t dst, const void* src) {
    asm volatile("cp.async.cg.shared.global [%0], [%1], 16;" :: "r"(dst), "l"(src));
}
#define CP_COMMIT() asm volatile("cp.async.commit_group;" ::: "memory")
#define CP_WAIT0()  asm volatile("cp.async.wait_group 0;" ::: "memory")

__device__ __forceinline__ void split_store(char* Ah, char* Al, int r, int q,
                                            float x0, float x1, float x2, float x3) {
    __nv_bfloat16 h0 = __float2bfloat16(x0), h1 = __float2bfloat16(x1);
    __nv_bfloat16 h2 = __float2bfloat16(x2), h3 = __float2bfloat16(x3);
    __nv_bfloat16 l0 = __float2bfloat16(x0 - __bfloat162float(h0));
    __nv_bfloat16 l1 = __float2bfloat16(x1 - __bfloat162float(h1));
    __nv_bfloat16 l2 = __float2bfloat16(x2 - __bfloat162float(h2));
    __nv_bfloat16 l3 = __float2bfloat16(x3 - __bfloat162float(h3));
    __nv_bfloat162 p;
    char* dh = Ah + r * ROWB + q * 8;
    char* dl = Al + r * ROWB + q * 8;
    p.x = h0; p.y = h1; *(__nv_bfloat162*)dh = p;
    p.x = h2; p.y = h3; *(__nv_bfloat162*)(dh + 4) = p;
    p.x = l0; p.y = l1; *(__nv_bfloat162*)dl = p;
    p.x = l2; p.y = l3; *(__nv_bfloat162*)(dl + 4) = p;
}

// ---------------------------------------------------------------------------
// k0 / kt / k1: unchanged proven pre-pass kernels
// ---------------------------------------------------------------------------
__global__ void __launch_bounds__(256)
k0_wconv(const float* __restrict__ Wv1, const float* __restrict__ Wv2)
{
    int idx = blockIdx.x * 256 + threadIdx.x;
    if (idx < 512 * 512) {
        int c = idx >> 9, k = idx & 511;
        float v = Wv1[idx];
        __nv_bfloat16 h = __float2bfloat16(v);
        __nv_bfloat16 l = __float2bfloat16(v - __bfloat162float(h));
        int nc = c >> 7, nl = c & 127, kc = k >> 5, kk = k & 31;
        size_t d = ((size_t)(nc * 16 + kc) * 128 + nl) * 32 + kk;
        g_W1h[d] = h; g_W1l[d] = l;
    } else if (idx < 512 * 512 + 256 * 512) {
        int e = idx - 512 * 512;
        int j = e >> 9, k = e & 511;
        float v = Wv2[e];
        __nv_bfloat16 h = __float2bfloat16(v);
        __nv_bfloat16 l = __float2bfloat16(v - __bfloat162float(h));
        int nc = j >> 7, nl = j & 127, kc = k >> 5, kk = k & 31;
        size_t d = ((size_t)(nc * 16 + kc) * 128 + nl) * 32 + kk;
        g_W2h[d] = h; g_W2l[d] = l;
    }
}

__global__ void __launch_bounds__(256)
kt_trans(const float* __restrict__ Wb, const float* __restrict__ Wc)
{
    int idx = blockIdx.x * 256 + threadIdx.x;
    if (idx < 128 * 256) {
        int k4 = idx >> 8, j = idx & 255;
        const float* s = Wb + (size_t)j * VD_ + k4 * 4;
        g_WbT4[idx] = make_float4(s[0], s[1], s[2], s[3]);
    } else if (idx < 128 * 256 + 64 * 512) {
        int e = idx - 128 * 256;
        int k4 = e >> 9, c = e & 511;
        const float* s = Wc + (size_t)c * HD_ + k4 * 4;
        g_WcT4[e] = make_float4(s[0], s[1], s[2], s[3]);
    }
}

__global__ void __launch_bounds__(256)
k1_audio(const float* __restrict__ audio,
         const float* __restrict__ Wa1, const float* __restrict__ ba1,
         const float* __restrict__ Wa2, const float* __restrict__ ba2)
{
    __shared__ __align__(16) float af[32][AD_];
    const int tid = threadIdx.x;
    const int bt0 = blockIdx.x * 32;

    for (int idx = tid; idx < 32 * AD_; idx += 256) {
        int i = idx >> 7, k = idx & 127;
        int bt = bt0 + i;
        int b = bt / T_, t = bt - b * T_;
        af[i][k] = audio[((size_t)t * B_ + b) * AD_ + k];
    }
    __syncthreads();

    for (int c = tid; c < VD_; c += 256) {
        const float4* w4 = (const float4*)(Wa1 + (size_t)c * AD_);
        float acc[32];
#pragma unroll
        for (int i = 0; i < 32; ++i) acc[i] = 0.f;
        for (int k4 = 0; k4 < AD_ / 4; ++k4) {
            float4 w = w4[k4];
#pragma unroll
            for (int i = 0; i < 32; ++i) {
                float4 v = *(const float4*)&af[i][k4 * 4];
                acc[i] += v.x * w.x + v.y * w.y + v.z * w.z + v.w * w.w;
            }
        }
        float bias = ba1[c];
#pragma unroll
        for (int i = 0; i < 32; ++i)
            g_aq1[(size_t)(bt0 + i) * VD_ + c] = fmaxf(acc[i] + bias, 0.f);
    }
    {
        int j = tid;
        const float4* w4 = (const float4*)(Wa2 + (size_t)j * AD_);
        float acc[32];
#pragma unroll
        for (int i = 0; i < 32; ++i) acc[i] = 0.f;
        for (int k4 = 0; k4 < AD_ / 4; ++k4) {
            float4 w = w4[k4];
#pragma unroll
            for (int i = 0; i < 32; ++i) {
                float4 v = *(const float4*)&af[i][k4 * 4];
                acc[i] += v.x * w.x + v.y * w.y + v.z * w.z + v.w * w.w;
            }
        }
        float bias = ba2[j];
#pragma unroll
        for (int i = 0; i < 32; ++i)
            g_aq2[(size_t)(bt0 + i) * HD_ + j] = fmaxf(acc[i] + bias, 0.f);
    }
}

// ===========================================================================
// g1: GEMM1, M=112 (2 clips packed) x N=128, warp grid 2(M) x 4(N):
//     wm=0 owns A tiles 0-3, wm=1 owns tiles 4-6; each warp a 32-wide N slice.
//     ldmx4/CTA/chunk: 176 (was 256). MMA count unchanged.
// SMEM/buffer: A_h@0(8960) A_l@8960 W_h@17920(10240) W_l@28160(10240)
// ===========================================================================
#define G1_AL   8960
#define G1_WH   17920
#define G1_WL   28160
#define G1_BUF  38400
#define SMEM_G1 76800

__global__ void __launch_bounds__(256, 2)
g1_mma(const float* __restrict__ video, const float* __restrict__ bv1)
{
    extern __shared__ char sm[];
    const int tid = threadIdx.x, wid = tid >> 5, lane = tid & 31;
    const int wm = wid >> 2, wn = wid & 3;
    const int nc = blockIdx.x, bt0 = blockIdx.y * 2;
    const uint32_t aBase = smem_u32(sm);

    const int mtN = 4 - wm;               // wm=0: tiles 0-3, wm=1: tiles 4-6

    float acc[4][2][2][4];                // [mt][np][sub][4]
#pragma unroll
    for (int a = 0; a < 4; ++a)
#pragma unroll
        for (int b = 0; b < 2; ++b)
#pragma unroll
            for (int c = 0; c < 2; ++c)
#pragma unroll
                for (int d = 0; d < 4; ++d) acc[a][b][c][d] = 0.f;

    // zero pad rows (49-55, 105-111) in both buffers, hi+lo: 14 rows x 16 words
    if (tid < 224) {
        int rr = tid >> 4, w = (tid & 15) * 4;
        int r = (rr < 7) ? (49 + rr) : (98 + rr);
#pragma unroll
        for (int b = 0; b < 2; ++b) {
            *(uint32_t*)(sm + b * G1_BUF + r * ROWB + w) = 0u;
            *(uint32_t*)(sm + b * G1_BUF + G1_AL + r * ROWB + w) = 0u;
        }
    }

    // A conversion: 784 float4 items (2 clips x 49 rows x 8 q) over 256 threads
    int pr_[4], q_[4];
    const float* vr_[4];
#pragma unroll
    for (int s = 0; s < 4; ++s) {
        int i = tid + s * 256;
        if (i >= 784) i = 0;
        int r = i >> 3, q = i & 7;
        int clip = (r >= 49);
        int h = r - clip * 49;
        pr_[s] = r + clip * 7;            // clip1 at phys rows 56..104
        q_[s] = q;
        vr_[s] = video + ((size_t)(bt0 + clip) * HW_ + h) * VD_ + q * 4;
    }
    const bool has3 = (tid < 16);

    // per-lane ldmatrix offsets (within a buffer)
    // A: warp M base = wm*64 rows; tile mt adds mt*MT_STRIDE
    const uint32_t oA = (uint32_t)((wm * 64 + (lane & 15)) * ROWB
                      + ((lane >> 4) & 1) * 16);
    // B: warp N base = wn*32 rows; np adds np*MT_STRIDE
    const uint32_t oB = G1_WH
                      + (uint32_t)((wn * 32 + (lane & 7) + ((lane >> 4) & 1) * 8) * ROWB
                      + ((lane >> 3) & 1) * 16);

    const __nv_bfloat16* wH = g_W1h + (size_t)nc * 16 * CHUNK_ELEMS;
    const __nv_bfloat16* wL = g_W1l + (size_t)nc * 16 * CHUNK_ELEMS;

    auto issue_w = [&](uint32_t dstBase, int kc) {
        const char* sH = (const char*)(wH + (size_t)kc * CHUNK_ELEMS);
        const char* sL = (const char*)(wL + (size_t)kc * CHUNK_ELEMS);
#pragma unroll
        for (int i = tid; i < 512; i += 256) {
            int r = i >> 2, qq = i & 3;
            uint32_t dof = (uint32_t)(r * ROWB + qq * 16);
            int sof = r * 64 + qq * 16;
            cp16(dstBase + G1_WH + dof, sH + sof);
            cp16(dstBase + G1_WL + dof, sL + sof);
        }
    };

    // prologue: chunk 0 -> buf0
    {
#pragma unroll
        for (int s = 0; s < 3; ++s) {
            float4 v = *(const float4*)vr_[s];
            split_store(sm, sm + G1_AL, pr_[s], q_[s], v.x, v.y, v.z, v.w);
        }
        if (has3) {
            float4 v = *(const float4*)vr_[3];
            split_store(sm, sm + G1_AL, pr_[3], q_[3], v.x, v.y, v.z, v.w);
        }
        issue_w(aBase, 0);
        CP_COMMIT();
    }

    for (int kc = 0; kc < 16; ++kc) {
        const int p = kc & 1;
        const uint32_t bp = aBase + p * G1_BUF;
        char* bq = sm + (p ^ 1) * G1_BUF;
        CP_WAIT0();
        __syncthreads();

        float4 pv0, pv1, pv2;
        if (kc < 15) {
            issue_w(aBase + (p ^ 1) * G1_BUF, kc + 1);
            CP_COMMIT();
            pv0 = *(const float4*)(vr_[0] + (kc + 1) * 32);
            pv1 = *(const float4*)(vr_[1] + (kc + 1) * 32);
            pv2 = *(const float4*)(vr_[2] + (kc + 1) * 32);
        }

        // MMA on chunk kc
#pragma unroll
        for (int ks = 0; ks < 2; ++ks) {
            uint32_t bh[2][4], bl[2][4];
#pragma unroll
            for (int np = 0; np < 2; ++np) {
                ldmx4(bp + oB + np * MT_STRIDE + ks * 32, bh[np]);
                ldmx4(bp + oB + (G1_WL - G1_WH) + np * MT_STRIDE + ks * 32, bl[np]);
            }
#pragma unroll
            for (int mt = 0; mt < 4; ++mt) {
                if (mt >= mtN) break;
                uint32_t ah[4], al[4];
                ldmx4(bp + oA + mt * MT_STRIDE + ks * 32, ah);
                ldmx4(bp + G1_AL + oA + mt * MT_STRIDE + ks * 32, al);
#pragma unroll
                for (int np = 0; np < 2; ++np)
#pragma unroll
                    for (int sub = 0; sub < 2; ++sub) {
                        int s = sub * 2;
                        mma_bf16(acc[mt][np][sub], ah, bh[np][s], bh[np][s + 1]);
                        mma_bf16(acc[mt][np][sub], al, bh[np][s], bh[np][s + 1]);
                        mma_bf16(acc[mt][np][sub], ah, bl[np][s], bl[np][s + 1]);
                    }
            }
        }

        // convert A(kc+1) -> buffer p^1 (slots 0-2 from regs, slot 3 direct)
        if (kc < 15) {
            split_store(bq, bq + G1_AL, pr_[0], q_[0], pv0.x, pv0.y, pv0.z, pv0.w);
            split_store(bq, bq + G1_AL, pr_[1], q_[1], pv1.x, pv1.y, pv1.z, pv1.w);
            split_store(bq, bq + G1_AL, pr_[2], q_[2], pv2.x, pv2.y, pv2.z, pv2.w);
            if (has3) {
                float4 v = *(const float4*)(vr_[3] + (kc + 1) * 32);
                split_store(bq, bq + G1_AL, pr_[3], q_[3], v.x, v.y, v.z, v.w);
            }
        }
    }
    __syncthreads();   // smem free for epilogue reuse

    // stage relu(D + bias) into smem [112][132]  (59136 B <= 76800)
    float* stage = (float*)sm;
#pragma unroll
    for (int mt = 0; mt < 4; ++mt) {
        if (mt >= mtN) break;
#pragma unroll
        for (int np = 0; np < 2; ++np)
#pragma unroll
            for (int sub = 0; sub < 2; ++sub) {
                int r0 = wm * 64 + mt * 16 + (lane >> 2);
                int c0 = wn * 32 + np * 16 + sub * 8 + (lane & 3) * 2;
                float b0 = bv1[nc * 128 + c0], b1 = bv1[nc * 128 + c0 + 1];
                stage[r0 * 132 + c0]           = fmaxf(acc[mt][np][sub][0] + b0, 0.f);
                stage[r0 * 132 + c0 + 1]       = fmaxf(acc[mt][np][sub][1] + b1, 0.f);
                stage[(r0 + 8) * 132 + c0]     = fmaxf(acc[mt][np][sub][2] + b0, 0.f);
                stage[(r0 + 8) * 132 + c0 + 1] = fmaxf(acc[mt][np][sub][3] + b1, 0.f);
            }
    }
    __syncthreads();

    {
        int clip = tid >> 7, col = tid & 127;
        float s = 0.f;
#pragma unroll
        for (int h = 0; h < HW_; ++h) s += stage[(clip * 56 + h) * 132 + col];
        int bt = bt0 + clip, c = nc * 128 + col;
        g_m1[(size_t)bt * VD_ + c] =
            g_aq1[(size_t)bt * VD_ + c] * s * (1.f / 49.f);
    }
}

// ---------------------------------------------------------------------------
// k3: channel-attention MLP (R11-proven coalesced variant)
// ---------------------------------------------------------------------------
__global__ void __launch_bounds__(256)
k3_catt(const float* __restrict__ bb, const float* __restrict__ bc)
{
    __shared__ __align__(16) float4 m1s4[16 * 128];
    __shared__ __align__(16) float t1s[16][HD_];
    const int tid = threadIdx.x;
    const int bt0 = blockIdx.x * 16;

    {
        const float4* src = (const float4*)(g_m1 + (size_t)bt0 * VD_);
        for (int i = tid; i < 16 * 128; i += 256) m1s4[i] = src[i];
    }
    __syncthreads();
    {
        const int j = tid;
        float acc[16];
#pragma unroll
        for (int i = 0; i < 16; ++i) acc[i] = 0.f;
        for (int k4 = 0; k4 < 128; ++k4) {
            float4 w = g_WbT4[k4 * 256 + j];
#pragma unroll
            for (int i = 0; i < 16; ++i) {
                float4 v = m1s4[i * 128 + k4];
                acc[i] += v.x * w.x + v.y * w.y + v.z * w.z + v.w * w.w;
            }
        }
        float bias = bb[j];
#pragma unroll
        for (int i = 0; i < 16; ++i) t1s[i][j] = fmaxf(acc[i] + bias, 0.f);
    }
    __syncthreads();
    {
        const int c0 = tid, c1 = tid + 256;
        float acc0[16], acc1[16];
#pragma unroll
        for (int i = 0; i < 16; ++i) { acc0[i] = 0.f; acc1[i] = 0.f; }
        for (int k4 = 0; k4 < 64; ++k4) {
            float4 w0 = g_WcT4[k4 * 512 + c0];
            float4 w1 = g_WcT4[k4 * 512 + c1];
#pragma unroll
            for (int i = 0; i < 16; ++i) {
                float4 v = *(const float4*)&t1s[i][k4 * 4];
                acc0[i] += v.x * w0.x + v.y * w0.y + v.z * w0.z + v.w * w0.w;
                acc1[i] += v.x * w1.x + v.y * w1.y + v.z * w1.z + v.w * w1.w;
            }
        }
        float b0 = bc[c0], b1 = bc[c1];
#pragma unroll
        for (int i = 0; i < 16; ++i) {
            float x0 = acc0[i] + b0, x1 = acc1[i] + b1;
            g_scale[(size_t)(bt0 + i) * VD_ + c0] = 1.f + 1.f / (1.f + expf(-x0));
            g_scale[(size_t)(bt0 + i) * VD_ + c1] = 1.f + 1.f / (1.f + expf(-x1));
        }
    }
}

// ===========================================================================
// g2: exact R16 path — M=64 (one clip), N=256, double-buffered K=32,
//     A reg-prefetch, fused relu/(aq2*Ws)/tanh/softmax/output epilogue.
// ===========================================================================
#define G2_AL   5120
#define G2_WH   10240
#define G2_WL   30720
#define G2_BUF  51200
#define SMEM_G2 102400

__global__ void __launch_bounds__(256, 2)
g2_mma(const float* __restrict__ video, const float* __restrict__ bv2,
       const float* __restrict__ Ws, const float* __restrict__ bs,
       float* __restrict__ out)
{
    extern __shared__ char sm[];
    __shared__ float u_s[256];
    __shared__ __align__(16) float s_scale[512];
    __shared__ float part[64];
    __shared__ float swt[64];
    __shared__ float smx, sdn;
    const int tid = threadIdx.x, wid = tid >> 5, lane = tid & 31;
    const int wm = wid >> 2, wn = wid & 3;
    const int bt = blockIdx.x;
    const uint32_t aBase = smem_u32(sm);

    u_s[tid] = g_aq2[(size_t)bt * HD_ + tid] * Ws[tid];
    s_scale[tid]       = g_scale[(size_t)bt * VD_ + tid];
    s_scale[tid + 256] = g_scale[(size_t)bt * VD_ + tid + 256];
    if (tid < 64) part[tid] = 0.f;
    __syncthreads();

    float acc[2][8][4];
#pragma unroll
    for (int a = 0; a < 2; ++a)
#pragma unroll
        for (int b = 0; b < 8; ++b)
#pragma unroll
            for (int c = 0; c < 4; ++c) acc[a][b][c] = 0.f;

    if (tid < 240) {
        int r = 49 + tid / 16, w = (tid & 15) * 4;
#pragma unroll
        for (int b = 0; b < 2; ++b) {
            *(uint32_t*)(sm + b * G2_BUF + r * ROWB + w) = 0u;
            *(uint32_t*)(sm + b * G2_BUF + G2_AL + r * ROWB + w) = 0u;
        }
    }

    const int i0 = tid, i1 = tid + 256;
    const int r0_ = i0 >> 3, q0 = i0 & 7;
    const int r1_ = i1 >> 3, q1 = i1 & 7;
    const bool has1 = (i1 < 392);
    const float* vrow0 = video + ((size_t)bt * HW_ + r0_) * VD_ + q0 * 4;
    const float* vrow1 = video + ((size_t)bt * HW_ + (has1 ? r1_ : 0)) * VD_ + q1 * 4;

    const uint32_t oAh = (uint32_t)((wm * 32 + (lane & 15)) * ROWB
                        + ((lane >> 4) & 1) * 16);
    const uint32_t oBh = G2_WH
                        + (uint32_t)((wn * 64 + (lane & 7) + ((lane >> 4) & 1) * 8) * ROWB
                        + ((lane >> 3) & 1) * 16);

    auto issue_w = [&](uint32_t dstBase, int kc) {
        const char* sH0 = (const char*)(g_W2h + (size_t)kc * CHUNK_ELEMS);
        const char* sL0 = (const char*)(g_W2l + (size_t)kc * CHUNK_ELEMS);
        const char* sH1 = (const char*)(g_W2h + (size_t)(16 + kc) * CHUNK_ELEMS);
        const char* sL1 = (const char*)(g_W2l + (size_t)(16 + kc) * CHUNK_ELEMS);
#pragma unroll
        for (int i = tid; i < 512; i += 256) {
            int r = i >> 2, qq = i & 3;
            uint32_t dof = (uint32_t)(r * ROWB + qq * 16);
            int sof = r * 64 + qq * 16;
            cp16(dstBase + G2_WH + dof,         sH0 + sof);
            cp16(dstBase + G2_WH + 10240 + dof, sH1 + sof);
            cp16(dstBase + G2_WL + dof,         sL0 + sof);
            cp16(dstBase + G2_WL + 10240 + dof, sL1 + sof);
        }
    };

    {
        float4 v0 = *(const float4*)vrow0;
        float4 v1 = has1 ? *(const float4*)vrow1 : make_float4(0.f, 0.f, 0.f, 0.f);
        {
            float4 s0 = *(const float4*)(s_scale + q0 * 4);
            v0.x *= s0.x; v0.y *= s0.y; v0.z *= s0.z; v0.w *= s0.w;
            if (has1) {
                float4 s1 = *(const float4*)(s_scale + q1 * 4);
                v1.x *= s1.x; v1.y *= s1.y; v1.z *= s1.z; v1.w *= s1.w;
            }
        }
        split_store(sm, sm + G2_AL, r0_, q0, v0.x, v0.y, v0.z, v0.w);
        if (has1) split_store(sm, sm + G2_AL, r1_, q1, v1.x, v1.y, v1.z, v1.w);
        issue_w(aBase, 0);
        CP_COMMIT();
    }

    for (int kc = 0; kc < 16; ++kc) {
        const int p = kc & 1;
        const uint32_t bp = aBase + p * G2_BUF;
        char* bq = sm + (p ^ 1) * G2_BUF;
        CP_WAIT0();
        __syncthreads();

        float4 v0, v1;
        if (kc < 15) {
            issue_w(aBase + (p ^ 1) * G2_BUF, kc + 1);
            CP_COMMIT();
            v0 = *(const float4*)(vrow0 + (kc + 1) * 32);
            if (has1) v1 = *(const float4*)(vrow1 + (kc + 1) * 32);
        }

#pragma unroll
        for (int ks = 0; ks < 2; ++ks) {
            uint32_t ah[2][4], al[2][4];
#pragma unroll
            for (int mt = 0; mt < 2; ++mt) {
                ldmx4(bp + oAh + mt * MT_STRIDE + ks * 32, ah[mt]);
                ldmx4(bp + G2_AL + oAh + mt * MT_STRIDE + ks * 32, al[mt]);
            }
#pragma unroll
            for (int np = 0; np < 4; ++np) {
                uint32_t bh4[4], bl4[4];
                ldmx4(bp + oBh + np * MT_STRIDE + ks * 32, bh4);
                ldmx4(bp + oBh + (G2_WL - G2_WH) + np * MT_STRIDE + ks * 32, bl4);
#pragma unroll
                for (int mt = 0; mt < 2; ++mt)
#pragma unroll
                    for (int sub = 0; sub < 2; ++sub) {
                        int nt = np * 2 + sub, s = sub * 2;
                        mma_bf16(acc[mt][nt], ah[mt], bh4[s], bh4[s + 1]);
                        mma_bf16(acc[mt][nt], al[mt], bh4[s], bh4[s + 1]);
                        mma_bf16(acc[mt][nt], ah[mt], bl4[s], bl4[s + 1]);
                    }
            }
        }

        if (kc < 15) {
            {
                float4 s0 = *(const float4*)(s_scale + (kc + 1) * 32 + q0 * 4);
                v0.x *= s0.x; v0.y *= s0.y; v0.z *= s0.z; v0.w *= s0.w;
                if (has1) {
                    float4 s1 = *(const float4*)(s_scale + (kc + 1) * 32 + q1 * 4);
                    v1.x *= s1.x; v1.y *= s1.y; v1.z *= s1.z; v1.w *= s1.w;
                }
            }
            split_store(bq, bq + G2_AL, r0_, q0, v0.x, v0.y, v0.z, v0.w);
            if (has1) split_store(bq, bq + G2_AL, r1_, q1, v1.x, v1.y, v1.z, v1.w);
        }
    }
    __syncthreads();

#pragma unroll
    for (int mt = 0; mt < 2; ++mt) {
        int r0 = wm * 32 + mt * 16 + (lane >> 2);
        float s0 = 0.f, s1 = 0.f;
#pragma unroll
        for (int nt = 0; nt < 8; ++nt) {
            int c0 = wn * 64 + nt * 8 + (lane & 3) * 2;
            float b0 = bv2[c0], b1 = bv2[c0 + 1];
            float u0 = u_s[c0], u1 = u_s[c0 + 1];
            s0 += fmaxf(acc[mt][nt][0] + b0, 0.f) * u0
                + fmaxf(acc[mt][nt][1] + b1, 0.f) * u1;
            s1 += fmaxf(acc[mt][nt][2] + b0, 0.f) * u0
                + fmaxf(acc[mt][nt][3] + b1, 0.f) * u1;
        }
        s0 += __shfl_xor_sync(0xffffffffu, s0, 1);
        s0 += __shfl_xor_sync(0xffffffffu, s0, 2);
        s1 += __shfl_xor_sync(0xffffffffu, s1, 1);
        s1 += __shfl_xor_sync(0xffffffffu, s1, 2);
        if ((lane & 3) == 0) {
            atomicAdd(&part[r0], s0);
            atomicAdd(&part[r0 + 8], s1);
        }
    }
    __syncthreads();

    if (tid < HW_) swt[tid] = tanhf(part[tid] + bs[0]);
    __syncthreads();
    if (tid == 0) {
        float mx = -1e30f;
        for (int h = 0; h < HW_; ++h) mx = fmaxf(mx, swt[h]);
        float den = 0.f;
        for (int h = 0; h < HW_; ++h) den += expf(swt[h] - mx);
        smx = mx; sdn = den;
    }
    __syncthreads();
    if (tid < HW_) swt[tid] = expf(swt[tid] - smx) / sdn;
    __syncthreads();

    for (int c = tid; c < VD_; c += 256) {
        float a = 0.f;
#pragma unroll 7
        for (int h = 0; h < HW_; ++h)
            a += swt[h] * video[((size_t)bt * HW_ + h) * VD_ + c];
        out[(size_t)bt * VD_ + c] = a * s_scale[c];
    }
}

// ---------------------------------------------------------------------------
// Launch
// ---------------------------------------------------------------------------
extern "C" void kernel_launch(void* const* d_in, const int* in_sizes, int n_in,
                              void* d_out, int out_size)
{
    const float* video = (const float*)d_in[0];
    const float* audio = (const float*)d_in[1];
    const float* Wv1   = (const float*)d_in[2];
    const float* bv1   = (const float*)d_in[3];
    const float* Wa1   = (const float*)d_in[4];
    const float* ba1   = (const float*)d_in[5];
    const float* Wb    = (const float*)d_in[6];
    const float* bb    = (const float*)d_in[7];
    const float* Wc    = (const float*)d_in[8];
    const float* bc    = (const float*)d_in[9];
    const float* Wv2   = (const float*)d_in[10];
    const float* bv2   = (const float*)d_in[11];
    const float* Wa2   = (const float*)d_in[12];
    const float* ba2   = (const float*)d_in[13];
    const float* Ws    = (const float*)d_in[14];
    const float* bs    = (const float*)d_in[15];
    float* out = (float*)d_out;

    cudaFuncSetAttribute(g1_mma, cudaFuncAttributeMaxDynamicSharedMemorySize, SMEM_G1);
    cudaFuncSetAttribute(g2_mma, cudaFuncAttributeMaxDynamicSharedMemorySize, SMEM_G2);

    k0_wconv<<<1536, 256>>>(Wv1, Wv2);
    kt_trans<<<256, 256>>>(Wb, Wc);
    k1_audio<<<BT_ / 32, 256>>>(audio, Wa1, ba1, Wa2, ba2);
    g1_mma<<<dim3(4, BT_ / 2), 256, SMEM_G1>>>(video, bv1);
    k3_catt<<<BT_ / 16, 256>>>(bb, bc);
    g2_mma<<<BT_, 256, SMEM_G2>>>(video, bv2, Ws, bs, out);
}